// round 15
// baseline (speedup 1.0000x reference)
#include <cuda_runtime.h>
#include <cuda_bf16.h>

#define B_ 4
#define L_ 16384
#define D_ 256
#define H_ 8
#define NCH 16
#define CHUNK 1024   // L_/NCH

// ---- scratch (static device allocations are allowed) ----
__device__ float g_Gpart[B_][NCH][3][128][128];  // ~12.5 MB
__device__ float g_spart[B_][NCH][D_];
__device__ float g_G[B_][D_][D_];
__device__ float g_s[B_][D_];
__device__ float g_T[B_][D_][D_];   // T = Wk @ G
__device__ float g_A[B_][D_][D_];
__device__ float g_r[B_][D_];
__device__ float g_c[B_][D_];
__device__ __nv_bfloat16 g_Mh[B_][D_][D_];   // M split
__device__ __nv_bfloat16 g_Ml[B_][D_][D_];

// ---- mma / ldmatrix helpers ----
__device__ __forceinline__ unsigned sptr(const void* p)
{
    return (unsigned)__cvta_generic_to_shared(p);
}
__device__ __forceinline__ void ldm4t(unsigned r[4], unsigned addr)
{
    asm volatile("ldmatrix.sync.aligned.m8n8.x4.trans.shared.b16 {%0,%1,%2,%3}, [%4];"
                 : "=r"(r[0]), "=r"(r[1]), "=r"(r[2]), "=r"(r[3]) : "r"(addr));
}
__device__ __forceinline__ void ldm4(unsigned r[4], unsigned addr)
{
    asm volatile("ldmatrix.sync.aligned.m8n8.x4.shared.b16 {%0,%1,%2,%3}, [%4];"
                 : "=r"(r[0]), "=r"(r[1]), "=r"(r[2]), "=r"(r[3]) : "r"(addr));
}
__device__ __forceinline__ void mma16816(float* c, const unsigned a[4],
                                         unsigned b0, unsigned b1)
{
    asm("mma.sync.aligned.m16n8k16.row.col.f32.bf16.bf16.f32 "
        "{%0,%1,%2,%3}, {%4,%5,%6,%7}, {%8,%9}, {%0,%1,%2,%3};"
        : "+f"(c[0]), "+f"(c[1]), "+f"(c[2]), "+f"(c[3])
        : "r"(a[0]), "r"(a[1]), "r"(a[2]), "r"(a[3]), "r"(b0), "r"(b1));
}
// split 8 fp32 -> 8 bf16 hi + 8 bf16 lo (packed)
__device__ __forceinline__ void split8(float4 a, float4 b, uint4& hi, uint4& lo)
{
    float v[8] = {a.x, a.y, a.z, a.w, b.x, b.y, b.z, b.w};
    unsigned h[4], l[4];
#pragma unroll
    for (int q = 0; q < 4; ++q) {
        __nv_bfloat162 ph, pl;
        ph.x = __float2bfloat16(v[2*q]);
        ph.y = __float2bfloat16(v[2*q+1]);
        pl.x = __float2bfloat16(v[2*q]   - __bfloat162float(ph.x));
        pl.y = __float2bfloat16(v[2*q+1] - __bfloat162float(ph.y));
        h[q] = *(unsigned*)&ph;
        l[q] = *(unsigned*)&pl;
    }
    hi = make_uint4(h[0], h[1], h[2], h[3]);
    lo = make_uint4(l[0], l[1], l[2], l[3]);
}

// ===========================================================================
// 1) partial G = x^T x via bf16 HMMA (hh + hl + lh); fp32->hi/lo split fused
//    into the smem loaders; colsum fused on diagonal tiles.
// ===========================================================================
__global__ __launch_bounds__(256, 2) void k_xtx(const float* __restrict__ x)
{
    const int chunk = blockIdx.x, tile3 = blockIdx.y, b = blockIdx.z;
    const int i0 = (tile3 == 2) ? 128 : 0;
    const int j0 = (tile3 == 0) ? 0 : 128;
    const bool diag = (tile3 != 1);

    __shared__ __nv_bfloat16 sA[2][2][16][136];   // [buf][hi/lo][k(l)][m(d)]
    __shared__ __nv_bfloat16 sB[2][2][16][136];

    const int t = threadIdx.x, lane = t & 31, w = t >> 5;
    const int wm = w >> 2, wn = w & 3;
    const int m0 = wm * 64, n0 = wn * 32;

    const float* xb = x + ((size_t)b * L_ + (size_t)chunk * CHUNK) * D_;
    const int lr = t >> 4, lc = (t & 15) * 8;    // slab load coords

    float acc[4][4][4];
#pragma unroll
    for (int i = 0; i < 4; ++i)
#pragma unroll
        for (int j = 0; j < 4; ++j)
#pragma unroll
            for (int q = 0; q < 4; ++q) acc[i][j][q] = 0.f;

    float scol[8];
#pragma unroll
    for (int q = 0; q < 8; ++q) scol[q] = 0.f;

    float4 va0, va1, vb0, vb1;
    {
        const float* rp = xb + (size_t)lr * D_;
        va0 = *(const float4*)(rp + i0 + lc);
        va1 = *(const float4*)(rp + i0 + lc + 4);
        if (!diag) {
            vb0 = *(const float4*)(rp + j0 + lc);
            vb1 = *(const float4*)(rp + j0 + lc + 4);
        } else {
            scol[0]+=va0.x; scol[1]+=va0.y; scol[2]+=va0.z; scol[3]+=va0.w;
            scol[4]+=va1.x; scol[5]+=va1.y; scol[6]+=va1.z; scol[7]+=va1.w;
        }
    }
    {
        uint4 hi, lo;
        split8(va0, va1, hi, lo);
        *(uint4*)&sA[0][0][lr][lc] = hi;
        *(uint4*)&sA[0][1][lr][lc] = lo;
        if (!diag) {
            split8(vb0, vb1, hi, lo);
            *(uint4*)&sB[0][0][lr][lc] = hi;
            *(uint4*)&sB[0][1][lr][lc] = lo;
        }
    }
    __syncthreads();

    const int aK = (lane & 7) + ((lane >> 4) << 3);
    const int aM = m0 + (lane & 8);
    const int bK = lane & 15;
    const int bNo = (lane >> 4) << 3;

    const int NS = CHUNK / 16;   // 64
    for (int s = 0; s < NS; ++s) {
        const int buf = s & 1;
        if (s + 1 < NS) {
            const float* rp = xb + (size_t)((s + 1) * 16 + lr) * D_;
            va0 = *(const float4*)(rp + i0 + lc);
            va1 = *(const float4*)(rp + i0 + lc + 4);
            if (!diag) {
                vb0 = *(const float4*)(rp + j0 + lc);
                vb1 = *(const float4*)(rp + j0 + lc + 4);
            } else {
                scol[0]+=va0.x; scol[1]+=va0.y; scol[2]+=va0.z; scol[3]+=va0.w;
                scol[4]+=va1.x; scol[5]+=va1.y; scol[6]+=va1.z; scol[7]+=va1.w;
            }
        }

        unsigned ah[4][4], al[4][4], bh[2][4], bl[2][4];
#pragma unroll
        for (int tm = 0; tm < 4; ++tm) {
            ldm4t(ah[tm], sptr(&sA[buf][0][aK][aM + tm * 16]));
            ldm4t(al[tm], sptr(&sA[buf][1][aK][aM + tm * 16]));
        }
        const __nv_bfloat16 (*pB)[16][136] = diag ? sA[buf] : sB[buf];
#pragma unroll
        for (int tp = 0; tp < 2; ++tp) {
            ldm4t(bh[tp], sptr(&pB[0][bK][n0 + tp * 16 + bNo]));
            ldm4t(bl[tp], sptr(&pB[1][bK][n0 + tp * 16 + bNo]));
        }
#pragma unroll
        for (int tm = 0; tm < 4; ++tm)
#pragma unroll
            for (int tp = 0; tp < 2; ++tp) {
                mma16816(acc[tm][2*tp],   ah[tm], bh[tp][0], bh[tp][1]);
                mma16816(acc[tm][2*tp+1], ah[tm], bh[tp][2], bh[tp][3]);
                mma16816(acc[tm][2*tp],   ah[tm], bl[tp][0], bl[tp][1]);
                mma16816(acc[tm][2*tp+1], ah[tm], bl[tp][2], bl[tp][3]);
                mma16816(acc[tm][2*tp],   al[tm], bh[tp][0], bh[tp][1]);
                mma16816(acc[tm][2*tp+1], al[tm], bh[tp][2], bh[tp][3]);
            }

        if (s + 1 < NS) {
            const int nb = buf ^ 1;
            uint4 hi, lo;
            split8(va0, va1, hi, lo);
            *(uint4*)&sA[nb][0][lr][lc] = hi;
            *(uint4*)&sA[nb][1][lr][lc] = lo;
            if (!diag) {
                split8(vb0, vb1, hi, lo);
                *(uint4*)&sB[nb][0][lr][lc] = hi;
                *(uint4*)&sB[nb][1][lr][lc] = lo;
            }
        }
        __syncthreads();
    }

    const int gr = lane >> 2, gc = (lane & 3) * 2;
#pragma unroll
    for (int tm = 0; tm < 4; ++tm)
#pragma unroll
        for (int tn = 0; tn < 4; ++tn) {
            int row = m0 + tm * 16 + gr;
            int col = n0 + tn * 8 + gc;
            *(float2*)&g_Gpart[b][chunk][tile3][row][col] =
                make_float2(acc[tm][tn][0], acc[tm][tn][1]);
            *(float2*)&g_Gpart[b][chunk][tile3][row + 8][col] =
                make_float2(acc[tm][tn][2], acc[tm][tn][3]);
        }

    if (diag) {   // reduce per-thread column sums (sA no longer needed)
        float* scr = (float*)sA;
#pragma unroll
        for (int q = 0; q < 8; ++q) scr[lr * 128 + lc + q] = scol[q];
        __syncthreads();
        if (t < 128) {
            float sp = 0.f;
#pragma unroll
            for (int r = 0; r < 16; ++r) sp += scr[r * 128 + t];
            g_spart[b][chunk][j0 + t] = sp;
        }
    }
}

// ===========================================================================
// 2) reduce partials -> G (mirroring tile 1), s
// ===========================================================================
__global__ __launch_bounds__(256) void k_reduce()
{
    const int bx = blockIdx.x, b = blockIdx.y;
    const int tile = bx >> 4, seg = bx & 15;
    const int i0 = (tile == 2) ? 128 : 0;
    const int j0 = (tile == 0) ? 0 : 128;
    const int t = threadIdx.x;

    const int e = seg * 256 + t;
    const int u = e >> 5, v4 = (e & 31) << 2;
    float4 sum = make_float4(0.f, 0.f, 0.f, 0.f);
#pragma unroll
    for (int ch = 0; ch < NCH; ++ch) {
        float4 p = *(const float4*)&g_Gpart[b][ch][tile][u][v4];
        sum.x += p.x; sum.y += p.y; sum.z += p.z; sum.w += p.w;
    }
    *(float4*)&g_G[b][i0 + u][j0 + v4] = sum;
    if (tile == 1) {
        g_G[b][j0 + v4 + 0][i0 + u] = sum.x;
        g_G[b][j0 + v4 + 1][i0 + u] = sum.y;
        g_G[b][j0 + v4 + 2][i0 + u] = sum.z;
        g_G[b][j0 + v4 + 3][i0 + u] = sum.w;
    }
    if (seg == 0 && tile != 1 && t < 128) {
        float s = 0.f;
#pragma unroll
        for (int ch = 0; ch < NCH; ++ch) s += g_spart[b][ch][j0 + t];
        g_s[b][j0 + t] = s;
    }
}

// ===========================================================================
// 3) T[b] = Wk @ G[b]    (NN, 64x64 tiles, 4x4 micro)
// ===========================================================================
__global__ __launch_bounds__(256) void k_T(const float* __restrict__ Wk)
{
    const int tile = blockIdx.x, b = blockIdx.y;
    const int i0 = (tile >> 2) << 6, j0 = (tile & 3) << 6;
    __shared__ float As[16][65];
    __shared__ __align__(16) float Bs[16][68];
    const int t = threadIdx.x, tx = t & 15, ty = t >> 4;
    const int au = t >> 2, aq = (t & 3) << 2;
    const int br = t >> 4, bc = (t & 15) << 2;

    float acc[4][4] = {};
    for (int k0 = 0; k0 < D_; k0 += 16) {
        float4 av = *(const float4*)&Wk[(i0 + au) * D_ + k0 + aq];
        As[aq+0][au] = av.x; As[aq+1][au] = av.y;
        As[aq+2][au] = av.z; As[aq+3][au] = av.w;
        *(float4*)&Bs[br][bc] = *(const float4*)&g_G[b][k0 + br][j0 + bc];
        __syncthreads();
#pragma unroll
        for (int kk = 0; kk < 16; ++kk) {
            float a[4], bb[4];
#pragma unroll
            for (int i = 0; i < 4; ++i) a[i] = As[kk][(ty << 2) + i];
#pragma unroll
            for (int j2 = 0; j2 < 4; ++j2) bb[j2] = Bs[kk][(tx << 2) + j2];
#pragma unroll
            for (int i = 0; i < 4; ++i)
#pragma unroll
                for (int j2 = 0; j2 < 4; ++j2) acc[i][j2] += a[i] * bb[j2];
        }
        __syncthreads();
    }
#pragma unroll
    for (int i = 0; i < 4; ++i) {
        float4 v = make_float4(acc[i][0], acc[i][1], acc[i][2], acc[i][3]);
        *(float4*)&g_T[b][i0 + (ty << 2) + i][j0 + (tx << 2)] = v;
    }
}

// ===========================================================================
// 4) per (b,h,half): P_h (32x32) incl. bias rank-1 terms, then a 16-column
//    slice of the A-block; r in half 0. 512 threads: halves every serial phase.
// ===========================================================================
__global__ __launch_bounds__(512, 2) void k_head(
    const float* __restrict__ Wq, const float* __restrict__ bq,
    const float* __restrict__ Wk, const float* __restrict__ bk,
    const float* __restrict__ Wv, const float* __restrict__ bv)
{
    const int h = blockIdx.x, b = blockIdx.y, half = blockIdx.z;
    const int hbase = h * 32;
    const int t = threadIdx.x, lane = t & 31, w = t >> 5;   // 16 warps
    const float invL = 1.f / (float)L_;

    __shared__ __align__(16) float Wvs[32][260];
    __shared__ __align__(16) float Ts[32][260];
    __shared__ __align__(16) float sv[256];
    __shared__ float uu[32], ww[32];
    __shared__ __align__(16) float Psm[32][36];

    if (t < 256) sv[t] = g_s[b][t];
#pragma unroll
    for (int e0 = 0; e0 < 4; ++e0) {
        int e = t + e0 * 512;            // 0..2047 float4
        int row = e >> 6, c4 = (e & 63) << 2;
        *(float4*)&Wvs[row][c4] = *(const float4*)&Wv[(hbase + row) * D_ + c4];
        *(float4*)&Ts[row][c4]  = *(const float4*)&g_T[b][hbase + row][c4];
    }
    __syncthreads();

    {   // uu/ww: 16 lanes per row
        int r = t >> 4, l16 = t & 15;
        float pk = 0.f, pv = 0.f;
#pragma unroll
        for (int k = l16 * 4; k < D_; k += 64) {
            float4 wk4 = *(const float4*)&Wk[(hbase + r) * D_ + k];
            float4 wv4 = *(const float4*)&Wvs[r][k];
            float4 s4  = *(const float4*)&sv[k];
            pk += wk4.x * s4.x + wk4.y * s4.y + wk4.z * s4.z + wk4.w * s4.w;
            pv += wv4.x * s4.x + wv4.y * s4.y + wv4.z * s4.z + wv4.w * s4.w;
        }
#pragma unroll
        for (int off = 8; off > 0; off >>= 1) {
            pk += __shfl_down_sync(0xffffffffu, pk, off);
            pv += __shfl_down_sync(0xffffffffu, pv, off);
        }
        if (l16 == 0) { uu[r] = pk; ww[r] = pv; }
    }
    __syncthreads();

#pragma unroll
    for (int q = 0; q < 2; ++q) {        // 16 warps cover 32 P rows
        int i = w + 16 * q;
        float d0 = 0.f, d1 = 0.f, d2 = 0.f, d3 = 0.f;
#pragma unroll
        for (int k4 = 0; k4 < 64; ++k4) {
            float4 tv = *(const float4*)&Ts[i][k4 << 2];
            float4 wv = *(const float4*)&Wvs[lane][k4 << 2];
            d0 += tv.x * wv.x; d1 += tv.y * wv.y;
            d2 += tv.z * wv.z; d3 += tv.w * wv.w;
        }
        float dot = (d0 + d1) + (d2 + d3);
        Psm[i][lane] = (dot + uu[i] * bv[hbase + lane] + bk[hbase + i] * ww[lane]) * invL
                       + bk[hbase + i] * bv[hbase + lane];
    }
    __syncthreads();

    // A-slice: this block's 16 cols split into 2 col-groups of 8 over 512 thr
    {
        const int row = t & 255, colg = t >> 8;       // colg 0..1
        const int base = half * 16 + colg * 8;
        float acc[8];
#pragma unroll
        for (int j = 0; j < 8; ++j) acc[j] = 0.f;
#pragma unroll 4
        for (int i = 0; i < 32; ++i) {
            float wq = Wq[(hbase + i) * D_ + row];
            float4 p0 = *(const float4*)&Psm[i][base];
            float4 p1 = *(const float4*)&Psm[i][base + 4];
            acc[0] += wq * p0.x; acc[1] += wq * p0.y;
            acc[2] += wq * p0.z; acc[3] += wq * p0.w;
            acc[4] += wq * p1.x; acc[5] += wq * p1.y;
            acc[6] += wq * p1.z; acc[7] += wq * p1.w;
        }
        *(float4*)&g_A[b][row][hbase + base] =
            make_float4(acc[0], acc[1], acc[2], acc[3]);
        *(float4*)&g_A[b][row][hbase + base + 4] =
            make_float4(acc[4], acc[5], acc[6], acc[7]);
    }

    if (half == 0 && t < 32) {
        float p = 0.f;
#pragma unroll
        for (int i = 0; i < 32; ++i) p += bq[hbase + i] * Psm[i][t];
        g_r[b][hbase + t] = p;
    }
}

// ===========================================================================
// 5) M[b] = A[b] @ Wfc^T  (NT, 64x64 tiles) -> bf16 hi/lo
// ===========================================================================
__global__ __launch_bounds__(256) void k_M(const float* __restrict__ Wfc)
{
    const int tile = blockIdx.x, b = blockIdx.y;
    const int i0 = (tile >> 2) << 6, j0 = (tile & 3) << 6;
    __shared__ float As[16][65];
    __shared__ float Bs[16][65];
    const int t = threadIdx.x, tx = t & 15, ty = t >> 4;
    const int au = t >> 2, aq = (t & 3) << 2;

    float acc[4][4] = {};
    for (int k0 = 0; k0 < D_; k0 += 16) {
        float4 av = *(const float4*)&g_A[b][i0 + au][k0 + aq];
        As[aq+0][au] = av.x; As[aq+1][au] = av.y;
        As[aq+2][au] = av.z; As[aq+3][au] = av.w;
        float4 bv4 = *(const float4*)&Wfc[(j0 + au) * D_ + k0 + aq];
        Bs[aq+0][au] = bv4.x; Bs[aq+1][au] = bv4.y;
        Bs[aq+2][au] = bv4.z; Bs[aq+3][au] = bv4.w;
        __syncthreads();
#pragma unroll
        for (int kk = 0; kk < 16; ++kk) {
            float a[4], bb[4];
#pragma unroll
            for (int i = 0; i < 4; ++i) a[i]  = As[kk][(ty << 2) + i];
#pragma unroll
            for (int j2 = 0; j2 < 4; ++j2) bb[j2] = Bs[kk][(tx << 2) + j2];
#pragma unroll
            for (int i = 0; i < 4; ++i)
#pragma unroll
                for (int j2 = 0; j2 < 4; ++j2) acc[i][j2] += a[i] * bb[j2];
        }
        __syncthreads();
    }
#pragma unroll
    for (int i = 0; i < 4; ++i) {
        int row = i0 + (ty << 2) + i, col = j0 + (tx << 2);
#pragma unroll
        for (int q = 0; q < 4; ++q) {
            float v = acc[i][q];
            __nv_bfloat16 hh = __float2bfloat16(v);
            g_Mh[b][row][col + q] = hh;
            g_Ml[b][row][col + q] = __float2bfloat16(v - __bfloat162float(hh));
        }
    }
}

// ===========================================================================
// 6) c[b] = Wfc @ r[b] + bfc
// ===========================================================================
__global__ __launch_bounds__(256) void k_c(const float* __restrict__ Wfc,
                                           const float* __restrict__ bfc)
{
    const int b = blockIdx.x, t = threadIdx.x;
    __shared__ float rs[256];
    rs[t] = g_r[b][t];
    __syncthreads();
    float p = 0.f;
#pragma unroll 8
    for (int e = 0; e < D_; ++e) p += Wfc[t * D_ + e] * rs[e];
    g_c[b][t] = p + bfc[t];
}

// ===========================================================================
// 7) final[b] = x[b] @ M[b] + 1 c[b]^T  via bf16 HMMA (hh + hl + lh);
//    fp32->hi/lo split of x fused into the smem loader.
// ===========================================================================
__global__ __launch_bounds__(256, 2) void k_out(const float* __restrict__ x,
                                                float* __restrict__ out)
{
    const int lt = blockIdx.x, dt = blockIdx.y, b = blockIdx.z;
    const int l0 = lt * 128, j0 = dt * 128;

    __shared__ __nv_bfloat16 sX[2][2][128][24];   // [buf][hi/lo][m(l)][k]
    __shared__ __nv_bfloat16 sM[2][2][16][136];   // [buf][hi/lo][k][n]

    const int t = threadIdx.x, lane = t & 31, w = t >> 5;
    const int wm = w >> 2, wn = w & 3;
    const int m0 = wm * 64, n0 = wn * 32;

    const float* xb = x + ((size_t)b * L_ + l0) * D_;

    const int xr = t >> 1, xk = (t & 1) * 8;     // X slab load coords
    const int mr = t >> 4, mc = (t & 15) * 8;    // M slab load coords

    float acc[4][4][4];
#pragma unroll
    for (int i = 0; i < 4; ++i)
#pragma unroll
        for (int j = 0; j < 4; ++j)
#pragma unroll
            for (int q = 0; q < 4; ++q) acc[i][j][q] = 0.f;

    float4 vx0, vx1;
    uint4 pMh, pMl;
    vx0 = *(const float4*)(xb + (size_t)xr * D_ + xk);
    vx1 = *(const float4*)(xb + (size_t)xr * D_ + xk + 4);
    pMh = *(const uint4*)&g_Mh[b][mr][j0 + mc];
    pMl = *(const uint4*)&g_Ml[b][mr][j0 + mc];
    {
        uint4 hi, lo;
        split8(vx0, vx1, hi, lo);
        *(uint4*)&sX[0][0][xr][xk] = hi;
        *(uint4*)&sX[0][1][xr][xk] = lo;
    }
    *(uint4*)&sM[0][0][mr][mc] = pMh;
    *(uint4*)&sM[0][1][mr][mc] = pMl;
    __syncthreads();

    const int aR = m0 + (lane & 7) + 8 * ((lane >> 3) & 1);
    const int aC = (lane >> 4) << 3;
    const int bK = lane & 15;
    const int bNo = (lane >> 4) << 3;

    const int NS = D_ / 16;   // 16
    for (int s = 0; s < NS; ++s) {
        const int buf = s & 1;
        if (s + 1 < NS) {
            int k0 = (s + 1) * 16;
            vx0 = *(const float4*)(xb + (size_t)xr * D_ + k0 + xk);
            vx1 = *(const float4*)(xb + (size_t)xr * D_ + k0 + xk + 4);
            pMh = *(const uint4*)&g_Mh[b][k0 + mr][j0 + mc];
            pMl = *(const uint4*)&g_Ml[b][k0 + mr][j0 + mc];
        }

        unsigned ah[4][4], al[4][4], bh[2][4], bl[2][4];
#pragma unroll
        for (int tm = 0; tm < 4; ++tm) {
            ldm4(ah[tm], sptr(&sX[buf][0][aR + tm * 16][aC]));
            ldm4(al[tm], sptr(&sX[buf][1][aR + tm * 16][aC]));
        }
#pragma unroll
        for (int tp = 0; tp < 2; ++tp) {
            ldm4t(bh[tp], sptr(&sM[buf][0][bK][n0 + tp * 16 + bNo]));
            ldm4t(bl[tp], sptr(&sM[buf][1][bK][n0 + tp * 16 + bNo]));
        }
#pragma unroll
        for (int tm = 0; tm < 4; ++tm)
#pragma unroll
            for (int tp = 0; tp < 2; ++tp) {
                mma16816(acc[tm][2*tp],   ah[tm], bh[tp][0], bh[tp][1]);
                mma16816(acc[tm][2*tp+1], ah[tm], bh[tp][2], bh[tp][3]);
                mma16816(acc[tm][2*tp],   ah[tm], bl[tp][0], bl[tp][1]);
                mma16816(acc[tm][2*tp+1], ah[tm], bl[tp][2], bl[tp][3]);
                mma16816(acc[tm][2*tp],   al[tm], bh[tp][0], bh[tp][1]);
                mma16816(acc[tm][2*tp+1], al[tm], bh[tp][2], bh[tp][3]);
            }

        if (s + 1 < NS) {
            const int nb = buf ^ 1;
            uint4 hi, lo;
            split8(vx0, vx1, hi, lo);
            *(uint4*)&sX[nb][0][xr][xk] = hi;
            *(uint4*)&sX[nb][1][xr][xk] = lo;
            *(uint4*)&sM[nb][0][mr][mc] = pMh;
            *(uint4*)&sM[nb][1][mr][mc] = pMl;
        }
        __syncthreads();
    }

    float* ob = out + (size_t)b * L_ * D_;
    const int gr = lane >> 2, gc = (lane & 3) * 2;
#pragma unroll
    for (int tm = 0; tm < 4; ++tm)
#pragma unroll
        for (int tn = 0; tn < 4; ++tn) {
            int row = l0 + m0 + tm * 16 + gr;
            int col = j0 + n0 + tn * 8 + gc;
            float2 cb = *(const float2*)&g_c[b][col];
            *(float2*)(ob + (size_t)row * D_ + col) =
                make_float2(acc[tm][tn][0] + cb.x, acc[tm][tn][1] + cb.y);
            *(float2*)(ob + (size_t)(row + 8) * D_ + col) =
                make_float2(acc[tm][tn][2] + cb.x, acc[tm][tn][3] + cb.y);
        }
}

// ===========================================================================
extern "C" void kernel_launch(void* const* d_in, const int* in_sizes, int n_in,
                              void* d_out, int out_size)
{
    const float* x   = (const float*)d_in[0];
    const float* Wq  = (const float*)d_in[1];
    const float* bq  = (const float*)d_in[2];
    const float* Wk  = (const float*)d_in[3];
    const float* bk  = (const float*)d_in[4];
    const float* Wv  = (const float*)d_in[5];
    const float* bv  = (const float*)d_in[6];
    const float* Wfc = (const float*)d_in[7];
    const float* bfc = (const float*)d_in[8];
    float* out = (float*)d_out;

    k_xtx<<<dim3(NCH, 3, B_), 256>>>(x);
    k_reduce<<<dim3(48, B_), 256>>>();
    k_T<<<dim3(16, B_), 256>>>(Wk);
    k_head<<<dim3(H_, B_, 2), 512>>>(Wq, bq, Wk, bk, Wv, bv);
    k_M<<<dim3(16, B_), 256>>>(Wfc);
    k_c<<<B_, 256>>>(Wfc, bfc);
    k_out<<<dim3(L_ / 128, 2, B_), 256>>>(x, out);
}

// round 16
// speedup vs baseline: 1.0395x; 1.0395x over previous
#include <cuda_runtime.h>
#include <cuda_bf16.h>

#define B_ 4
#define L_ 16384
#define D_ 256
#define H_ 8
#define NCH 16
#define CHUNK 1024   // L_/NCH

// ---- scratch (static device allocations are allowed) ----
__device__ float g_Gpart[B_][NCH][3][128][128];  // ~12.5 MB
__device__ float g_spart[B_][NCH][D_];
__device__ float g_G[B_][D_][D_];
__device__ float g_s[B_][D_];
__device__ float g_T[B_][D_][D_];   // T = Wk @ G
__device__ float g_A[B_][D_][D_];
__device__ float g_r[B_][D_];
__device__ float g_c[B_][D_];
__device__ __nv_bfloat16 g_Mh[B_][D_][D_];   // M split
__device__ __nv_bfloat16 g_Ml[B_][D_][D_];

// ---- mma / ldmatrix helpers ----
__device__ __forceinline__ unsigned sptr(const void* p)
{
    return (unsigned)__cvta_generic_to_shared(p);
}
__device__ __forceinline__ void ldm4t(unsigned r[4], unsigned addr)
{
    asm volatile("ldmatrix.sync.aligned.m8n8.x4.trans.shared.b16 {%0,%1,%2,%3}, [%4];"
                 : "=r"(r[0]), "=r"(r[1]), "=r"(r[2]), "=r"(r[3]) : "r"(addr));
}
__device__ __forceinline__ void ldm4(unsigned r[4], unsigned addr)
{
    asm volatile("ldmatrix.sync.aligned.m8n8.x4.shared.b16 {%0,%1,%2,%3}, [%4];"
                 : "=r"(r[0]), "=r"(r[1]), "=r"(r[2]), "=r"(r[3]) : "r"(addr));
}
__device__ __forceinline__ void mma16816(float* c, const unsigned a[4],
                                         unsigned b0, unsigned b1)
{
    asm("mma.sync.aligned.m16n8k16.row.col.f32.bf16.bf16.f32 "
        "{%0,%1,%2,%3}, {%4,%5,%6,%7}, {%8,%9}, {%0,%1,%2,%3};"
        : "+f"(c[0]), "+f"(c[1]), "+f"(c[2]), "+f"(c[3])
        : "r"(a[0]), "r"(a[1]), "r"(a[2]), "r"(a[3]), "r"(b0), "r"(b1));
}
// split 8 fp32 -> 8 bf16 hi + 8 bf16 lo (packed)
__device__ __forceinline__ void split8(float4 a, float4 b, uint4& hi, uint4& lo)
{
    float v[8] = {a.x, a.y, a.z, a.w, b.x, b.y, b.z, b.w};
    unsigned h[4], l[4];
#pragma unroll
    for (int q = 0; q < 4; ++q) {
        __nv_bfloat162 ph, pl;
        ph.x = __float2bfloat16(v[2*q]);
        ph.y = __float2bfloat16(v[2*q+1]);
        pl.x = __float2bfloat16(v[2*q]   - __bfloat162float(ph.x));
        pl.y = __float2bfloat16(v[2*q+1] - __bfloat162float(ph.y));
        h[q] = *(unsigned*)&ph;
        l[q] = *(unsigned*)&pl;
    }
    hi = make_uint4(h[0], h[1], h[2], h[3]);
    lo = make_uint4(l[0], l[1], l[2], l[3]);
}

// ===========================================================================
// 1) partial G = x^T x via bf16 HMMA (hh + hl + lh); fp32->hi/lo split fused
//    into the smem loaders; colsum fused on diagonal tiles.
// ===========================================================================
__global__ __launch_bounds__(256, 2) void k_xtx(const float* __restrict__ x)
{
    const int chunk = blockIdx.x, tile3 = blockIdx.y, b = blockIdx.z;
    const int i0 = (tile3 == 2) ? 128 : 0;
    const int j0 = (tile3 == 0) ? 0 : 128;
    const bool diag = (tile3 != 1);

    __shared__ __nv_bfloat16 sA[2][2][16][136];   // [buf][hi/lo][k(l)][m(d)]
    __shared__ __nv_bfloat16 sB[2][2][16][136];

    const int t = threadIdx.x, lane = t & 31, w = t >> 5;
    const int wm = w >> 2, wn = w & 3;
    const int m0 = wm * 64, n0 = wn * 32;

    const float* xb = x + ((size_t)b * L_ + (size_t)chunk * CHUNK) * D_;
    const int lr = t >> 4, lc = (t & 15) * 8;    // slab load coords

    float acc[4][4][4];
#pragma unroll
    for (int i = 0; i < 4; ++i)
#pragma unroll
        for (int j = 0; j < 4; ++j)
#pragma unroll
            for (int q = 0; q < 4; ++q) acc[i][j][q] = 0.f;

    float scol[8];
#pragma unroll
    for (int q = 0; q < 8; ++q) scol[q] = 0.f;

    float4 va0, va1, vb0, vb1;
    {
        const float* rp = xb + (size_t)lr * D_;
        va0 = *(const float4*)(rp + i0 + lc);
        va1 = *(const float4*)(rp + i0 + lc + 4);
        if (!diag) {
            vb0 = *(const float4*)(rp + j0 + lc);
            vb1 = *(const float4*)(rp + j0 + lc + 4);
        } else {
            scol[0]+=va0.x; scol[1]+=va0.y; scol[2]+=va0.z; scol[3]+=va0.w;
            scol[4]+=va1.x; scol[5]+=va1.y; scol[6]+=va1.z; scol[7]+=va1.w;
        }
    }
    {
        uint4 hi, lo;
        split8(va0, va1, hi, lo);
        *(uint4*)&sA[0][0][lr][lc] = hi;
        *(uint4*)&sA[0][1][lr][lc] = lo;
        if (!diag) {
            split8(vb0, vb1, hi, lo);
            *(uint4*)&sB[0][0][lr][lc] = hi;
            *(uint4*)&sB[0][1][lr][lc] = lo;
        }
    }
    __syncthreads();

    const int aK = (lane & 7) + ((lane >> 4) << 3);
    const int aM = m0 + (lane & 8);
    const int bK = lane & 15;
    const int bNo = (lane >> 4) << 3;

    const int NS = CHUNK / 16;   // 64
    for (int s = 0; s < NS; ++s) {
        const int buf = s & 1;
        if (s + 1 < NS) {
            const float* rp = xb + (size_t)((s + 1) * 16 + lr) * D_;
            va0 = *(const float4*)(rp + i0 + lc);
            va1 = *(const float4*)(rp + i0 + lc + 4);
            if (!diag) {
                vb0 = *(const float4*)(rp + j0 + lc);
                vb1 = *(const float4*)(rp + j0 + lc + 4);
            } else {
                scol[0]+=va0.x; scol[1]+=va0.y; scol[2]+=va0.z; scol[3]+=va0.w;
                scol[4]+=va1.x; scol[5]+=va1.y; scol[6]+=va1.z; scol[7]+=va1.w;
            }
        }

        unsigned ah[4][4], al[4][4], bh[2][4], bl[2][4];
#pragma unroll
        for (int tm = 0; tm < 4; ++tm) {
            ldm4t(ah[tm], sptr(&sA[buf][0][aK][aM + tm * 16]));
            ldm4t(al[tm], sptr(&sA[buf][1][aK][aM + tm * 16]));
        }
        const __nv_bfloat16 (*pB)[16][136] = diag ? sA[buf] : sB[buf];
#pragma unroll
        for (int tp = 0; tp < 2; ++tp) {
            ldm4t(bh[tp], sptr(&pB[0][bK][n0 + tp * 16 + bNo]));
            ldm4t(bl[tp], sptr(&pB[1][bK][n0 + tp * 16 + bNo]));
        }
#pragma unroll
        for (int tm = 0; tm < 4; ++tm)
#pragma unroll
            for (int tp = 0; tp < 2; ++tp) {
                mma16816(acc[tm][2*tp],   ah[tm], bh[tp][0], bh[tp][1]);
                mma16816(acc[tm][2*tp+1], ah[tm], bh[tp][2], bh[tp][3]);
                mma16816(acc[tm][2*tp],   ah[tm], bl[tp][0], bl[tp][1]);
                mma16816(acc[tm][2*tp+1], ah[tm], bl[tp][2], bl[tp][3]);
                mma16816(acc[tm][2*tp],   al[tm], bh[tp][0], bh[tp][1]);
                mma16816(acc[tm][2*tp+1], al[tm], bh[tp][2], bh[tp][3]);
            }

        if (s + 1 < NS) {
            const int nb = buf ^ 1;
            uint4 hi, lo;
            split8(va0, va1, hi, lo);
            *(uint4*)&sA[nb][0][lr][lc] = hi;
            *(uint4*)&sA[nb][1][lr][lc] = lo;
            if (!diag) {
                split8(vb0, vb1, hi, lo);
                *(uint4*)&sB[nb][0][lr][lc] = hi;
                *(uint4*)&sB[nb][1][lr][lc] = lo;
            }
        }
        __syncthreads();
    }

    const int gr = lane >> 2, gc = (lane & 3) * 2;
#pragma unroll
    for (int tm = 0; tm < 4; ++tm)
#pragma unroll
        for (int tn = 0; tn < 4; ++tn) {
            int row = m0 + tm * 16 + gr;
            int col = n0 + tn * 8 + gc;
            *(float2*)&g_Gpart[b][chunk][tile3][row][col] =
                make_float2(acc[tm][tn][0], acc[tm][tn][1]);
            *(float2*)&g_Gpart[b][chunk][tile3][row + 8][col] =
                make_float2(acc[tm][tn][2], acc[tm][tn][3]);
        }

    if (diag) {   // reduce per-thread column sums (sA no longer needed)
        float* scr = (float*)sA;
#pragma unroll
        for (int q = 0; q < 8; ++q) scr[lr * 128 + lc + q] = scol[q];
        __syncthreads();
        if (t < 128) {
            float sp = 0.f;
#pragma unroll
            for (int r = 0; r < 16; ++r) sp += scr[r * 128 + t];
            g_spart[b][chunk][j0 + t] = sp;
        }
    }
}

// ===========================================================================
// 2) reduce partials -> G (mirroring tile 1), s
// ===========================================================================
__global__ __launch_bounds__(256) void k_reduce()
{
    const int bx = blockIdx.x, b = blockIdx.y;
    const int tile = bx >> 4, seg = bx & 15;
    const int i0 = (tile == 2) ? 128 : 0;
    const int j0 = (tile == 0) ? 0 : 128;
    const int t = threadIdx.x;

    const int e = seg * 256 + t;
    const int u = e >> 5, v4 = (e & 31) << 2;
    float4 sum = make_float4(0.f, 0.f, 0.f, 0.f);
#pragma unroll
    for (int ch = 0; ch < NCH; ++ch) {
        float4 p = *(const float4*)&g_Gpart[b][ch][tile][u][v4];
        sum.x += p.x; sum.y += p.y; sum.z += p.z; sum.w += p.w;
    }
    *(float4*)&g_G[b][i0 + u][j0 + v4] = sum;
    if (tile == 1) {
        g_G[b][j0 + v4 + 0][i0 + u] = sum.x;
        g_G[b][j0 + v4 + 1][i0 + u] = sum.y;
        g_G[b][j0 + v4 + 2][i0 + u] = sum.z;
        g_G[b][j0 + v4 + 3][i0 + u] = sum.w;
    }
    if (seg == 0 && tile != 1 && t < 128) {
        float s = 0.f;
#pragma unroll
        for (int ch = 0; ch < NCH; ++ch) s += g_spart[b][ch][j0 + t];
        g_s[b][j0 + t] = s;
    }
}

// ===========================================================================
// 3) T[b] = Wk @ G[b]    (NN, 64x64 tiles, 4x4 micro)
// ===========================================================================
__global__ __launch_bounds__(256) void k_T(const float* __restrict__ Wk)
{
    const int tile = blockIdx.x, b = blockIdx.y;
    const int i0 = (tile >> 2) << 6, j0 = (tile & 3) << 6;
    __shared__ float As[16][65];
    __shared__ __align__(16) float Bs[16][68];
    const int t = threadIdx.x, tx = t & 15, ty = t >> 4;
    const int au = t >> 2, aq = (t & 3) << 2;
    const int br = t >> 4, bc = (t & 15) << 2;

    float acc[4][4] = {};
    for (int k0 = 0; k0 < D_; k0 += 16) {
        float4 av = *(const float4*)&Wk[(i0 + au) * D_ + k0 + aq];
        As[aq+0][au] = av.x; As[aq+1][au] = av.y;
        As[aq+2][au] = av.z; As[aq+3][au] = av.w;
        *(float4*)&Bs[br][bc] = *(const float4*)&g_G[b][k0 + br][j0 + bc];
        __syncthreads();
#pragma unroll
        for (int kk = 0; kk < 16; ++kk) {
            float a[4], bb[4];
#pragma unroll
            for (int i = 0; i < 4; ++i) a[i] = As[kk][(ty << 2) + i];
#pragma unroll
            for (int j2 = 0; j2 < 4; ++j2) bb[j2] = Bs[kk][(tx << 2) + j2];
#pragma unroll
            for (int i = 0; i < 4; ++i)
#pragma unroll
                for (int j2 = 0; j2 < 4; ++j2) acc[i][j2] += a[i] * bb[j2];
        }
        __syncthreads();
    }
#pragma unroll
    for (int i = 0; i < 4; ++i) {
        float4 v = make_float4(acc[i][0], acc[i][1], acc[i][2], acc[i][3]);
        *(float4*)&g_T[b][i0 + (ty << 2) + i][j0 + (tx << 2)] = v;
    }
}

// ===========================================================================
// 4) per (b,h,half): P_h (32x32) incl. bias rank-1 terms, then a 16-column
//    slice of the A-block (split over blockIdx.z for 2x occupancy); r in half 0.
// ===========================================================================
__global__ __launch_bounds__(256) void k_head(
    const float* __restrict__ Wq, const float* __restrict__ bq,
    const float* __restrict__ Wk, const float* __restrict__ bk,
    const float* __restrict__ Wv, const float* __restrict__ bv)
{
    const int h = blockIdx.x, b = blockIdx.y, half = blockIdx.z;
    const int hbase = h * 32;
    const int t = threadIdx.x, lane = t & 31, w = t >> 5;
    const float invL = 1.f / (float)L_;

    __shared__ __align__(16) float Wvs[32][260];
    __shared__ __align__(16) float Ts[32][260];
    __shared__ __align__(16) float sv[256];
    __shared__ float uu[32], ww[32];
    __shared__ __align__(16) float Psm[32][36];

    sv[t] = g_s[b][t];
#pragma unroll
    for (int e0 = 0; e0 < 8; ++e0) {
        int e = t + e0 * 256;
        int row = e >> 6, c4 = (e & 63) << 2;
        *(float4*)&Wvs[row][c4] = *(const float4*)&Wv[(hbase + row) * D_ + c4];
        *(float4*)&Ts[row][c4]  = *(const float4*)&g_T[b][hbase + row][c4];
    }
    __syncthreads();

    {
        int r = t >> 3, l8 = t & 7;
        float pk = 0.f, pv = 0.f;
#pragma unroll
        for (int k = l8 * 4; k < D_; k += 32) {
            float4 wk4 = *(const float4*)&Wk[(hbase + r) * D_ + k];
            float4 wv4 = *(const float4*)&Wvs[r][k];
            float4 s4  = *(const float4*)&sv[k];
            pk += wk4.x * s4.x + wk4.y * s4.y + wk4.z * s4.z + wk4.w * s4.w;
            pv += wv4.x * s4.x + wv4.y * s4.y + wv4.z * s4.z + wv4.w * s4.w;
        }
#pragma unroll
        for (int off = 4; off > 0; off >>= 1) {
            pk += __shfl_down_sync(0xffffffffu, pk, off);
            pv += __shfl_down_sync(0xffffffffu, pv, off);
        }
        if (l8 == 0) { uu[r] = pk; ww[r] = pv; }
    }
    __syncthreads();

#pragma unroll
    for (int q = 0; q < 4; ++q) {
        int i = w + 8 * q;
        float d0 = 0.f, d1 = 0.f, d2 = 0.f, d3 = 0.f;
#pragma unroll
        for (int k4 = 0; k4 < 64; ++k4) {
            float4 tv = *(const float4*)&Ts[i][k4 << 2];
            float4 wv = *(const float4*)&Wvs[lane][k4 << 2];
            d0 += tv.x * wv.x; d1 += tv.y * wv.y;
            d2 += tv.z * wv.z; d3 += tv.w * wv.w;
        }
        float dot = (d0 + d1) + (d2 + d3);
        Psm[i][lane] = (dot + uu[i] * bv[hbase + lane] + bk[hbase + i] * ww[lane]) * invL
                       + bk[hbase + i] * bv[hbase + lane];
    }
    __syncthreads();

    // A-slice: 16 columns (this block's half)
    {
        float acc[16];
#pragma unroll
        for (int j = 0; j < 16; ++j) acc[j] = 0.f;
#pragma unroll 4
        for (int i = 0; i < 32; ++i) {
            float wq = Wq[(hbase + i) * D_ + t];
#pragma unroll
            for (int j4 = 0; j4 < 4; ++j4) {
                float4 p4 = *(const float4*)&Psm[i][half * 16 + (j4 << 2)];
                acc[4*j4+0] += wq * p4.x; acc[4*j4+1] += wq * p4.y;
                acc[4*j4+2] += wq * p4.z; acc[4*j4+3] += wq * p4.w;
            }
        }
#pragma unroll
        for (int j4 = 0; j4 < 4; ++j4)
            *(float4*)&g_A[b][t][hbase + half * 16 + (j4 << 2)] =
                make_float4(acc[4*j4], acc[4*j4+1], acc[4*j4+2], acc[4*j4+3]);
    }

    if (half == 0 && t < 32) {
        float p = 0.f;
#pragma unroll
        for (int i = 0; i < 32; ++i) p += bq[hbase + i] * Psm[i][t];
        g_r[b][hbase + t] = p;
    }
}

// ===========================================================================
// 5) M[b] = A[b] @ Wfc^T  (NT, 64x64 tiles) -> bf16 hi/lo
// ===========================================================================
__global__ __launch_bounds__(256) void k_M(const float* __restrict__ Wfc)
{
    const int tile = blockIdx.x, b = blockIdx.y;
    const int i0 = (tile >> 2) << 6, j0 = (tile & 3) << 6;
    __shared__ float As[16][65];
    __shared__ float Bs[16][65];
    const int t = threadIdx.x, tx = t & 15, ty = t >> 4;
    const int au = t >> 2, aq = (t & 3) << 2;

    float acc[4][4] = {};
    for (int k0 = 0; k0 < D_; k0 += 16) {
        float4 av = *(const float4*)&g_A[b][i0 + au][k0 + aq];
        As[aq+0][au] = av.x; As[aq+1][au] = av.y;
        As[aq+2][au] = av.z; As[aq+3][au] = av.w;
        float4 bv4 = *(const float4*)&Wfc[(j0 + au) * D_ + k0 + aq];
        Bs[aq+0][au] = bv4.x; Bs[aq+1][au] = bv4.y;
        Bs[aq+2][au] = bv4.z; Bs[aq+3][au] = bv4.w;
        __syncthreads();
#pragma unroll
        for (int kk = 0; kk < 16; ++kk) {
            float a[4], bb[4];
#pragma unroll
            for (int i = 0; i < 4; ++i) a[i]  = As[kk][(ty << 2) + i];
#pragma unroll
            for (int j2 = 0; j2 < 4; ++j2) bb[j2] = Bs[kk][(tx << 2) + j2];
#pragma unroll
            for (int i = 0; i < 4; ++i)
#pragma unroll
                for (int j2 = 0; j2 < 4; ++j2) acc[i][j2] += a[i] * bb[j2];
        }
        __syncthreads();
    }
#pragma unroll
    for (int i = 0; i < 4; ++i) {
        int row = i0 + (ty << 2) + i, col = j0 + (tx << 2);
#pragma unroll
        for (int q = 0; q < 4; ++q) {
            float v = acc[i][q];
            __nv_bfloat16 hh = __float2bfloat16(v);
            g_Mh[b][row][col + q] = hh;
            g_Ml[b][row][col + q] = __float2bfloat16(v - __bfloat162float(hh));
        }
    }
}

// ===========================================================================
// 6) c[b] = Wfc @ r[b] + bfc
// ===========================================================================
__global__ __launch_bounds__(256) void k_c(const float* __restrict__ Wfc,
                                           const float* __restrict__ bfc)
{
    const int b = blockIdx.x, t = threadIdx.x;
    __shared__ float rs[256];
    rs[t] = g_r[b][t];
    __syncthreads();
    float p = 0.f;
#pragma unroll 8
    for (int e = 0; e < D_; ++e) p += Wfc[t * D_ + e] * rs[e];
    g_c[b][t] = p + bfc[t];
}

// ===========================================================================
// 7) final[b] = x[b] @ M[b] + 1 c[b]^T  via bf16 HMMA (hh + hl + lh);
//    fp32->hi/lo split of x fused into the smem loader.
// ===========================================================================
__global__ __launch_bounds__(256, 2) void k_out(const float* __restrict__ x,
                                                float* __restrict__ out)
{
    const int lt = blockIdx.x, dt = blockIdx.y, b = blockIdx.z;
    const int l0 = lt * 128, j0 = dt * 128;

    __shared__ __nv_bfloat16 sX[2][2][128][24];   // [buf][hi/lo][m(l)][k]
    __shared__ __nv_bfloat16 sM[2][2][16][136];   // [buf][hi/lo][k][n]

    const int t = threadIdx.x, lane = t & 31, w = t >> 5;
    const int wm = w >> 2, wn = w & 3;
    const int m0 = wm * 64, n0 = wn * 32;

    const float* xb = x + ((size_t)b * L_ + l0) * D_;

    const int xr = t >> 1, xk = (t & 1) * 8;     // X slab load coords
    const int mr = t >> 4, mc = (t & 15) * 8;    // M slab load coords

    float acc[4][4][4];
#pragma unroll
    for (int i = 0; i < 4; ++i)
#pragma unroll
        for (int j = 0; j < 4; ++j)
#pragma unroll
            for (int q = 0; q < 4; ++q) acc[i][j][q] = 0.f;

    float4 vx0, vx1;
    uint4 pMh, pMl;
    vx0 = *(const float4*)(xb + (size_t)xr * D_ + xk);
    vx1 = *(const float4*)(xb + (size_t)xr * D_ + xk + 4);
    pMh = *(const uint4*)&g_Mh[b][mr][j0 + mc];
    pMl = *(const uint4*)&g_Ml[b][mr][j0 + mc];
    {
        uint4 hi, lo;
        split8(vx0, vx1, hi, lo);
        *(uint4*)&sX[0][0][xr][xk] = hi;
        *(uint4*)&sX[0][1][xr][xk] = lo;
    }
    *(uint4*)&sM[0][0][mr][mc] = pMh;
    *(uint4*)&sM[0][1][mr][mc] = pMl;
    __syncthreads();

    const int aR = m0 + (lane & 7) + 8 * ((lane >> 3) & 1);
    const int aC = (lane >> 4) << 3;
    const int bK = lane & 15;
    const int bNo = (lane >> 4) << 3;

    const int NS = D_ / 16;   // 16
    for (int s = 0; s < NS; ++s) {
        const int buf = s & 1;
        if (s + 1 < NS) {
            int k0 = (s + 1) * 16;
            vx0 = *(const float4*)(xb + (size_t)xr * D_ + k0 + xk);
            vx1 = *(const float4*)(xb + (size_t)xr * D_ + k0 + xk + 4);
            pMh = *(const uint4*)&g_Mh[b][k0 + mr][j0 + mc];
            pMl = *(const uint4*)&g_Ml[b][k0 + mr][j0 + mc];
        }

        unsigned ah[4][4], al[4][4], bh[2][4], bl[2][4];
#pragma unroll
        for (int tm = 0; tm < 4; ++tm) {
            ldm4(ah[tm], sptr(&sX[buf][0][aR + tm * 16][aC]));
            ldm4(al[tm], sptr(&sX[buf][1][aR + tm * 16][aC]));
        }
#pragma unroll
        for (int tp = 0; tp < 2; ++tp) {
            ldm4t(bh[tp], sptr(&sM[buf][0][bK][n0 + tp * 16 + bNo]));
            ldm4t(bl[tp], sptr(&sM[buf][1][bK][n0 + tp * 16 + bNo]));
        }
#pragma unroll
        for (int tm = 0; tm < 4; ++tm)
#pragma unroll
            for (int tp = 0; tp < 2; ++tp) {
                mma16816(acc[tm][2*tp],   ah[tm], bh[tp][0], bh[tp][1]);
                mma16816(acc[tm][2*tp+1], ah[tm], bh[tp][2], bh[tp][3]);
                mma16816(acc[tm][2*tp],   ah[tm], bl[tp][0], bl[tp][1]);
                mma16816(acc[tm][2*tp+1], ah[tm], bl[tp][2], bl[tp][3]);
                mma16816(acc[tm][2*tp],   al[tm], bh[tp][0], bh[tp][1]);
                mma16816(acc[tm][2*tp+1], al[tm], bh[tp][2], bh[tp][3]);
            }

        if (s + 1 < NS) {
            const int nb = buf ^ 1;
            uint4 hi, lo;
            split8(vx0, vx1, hi, lo);
            *(uint4*)&sX[nb][0][xr][xk] = hi;
            *(uint4*)&sX[nb][1][xr][xk] = lo;
            *(uint4*)&sM[nb][0][mr][mc] = pMh;
            *(uint4*)&sM[nb][1][mr][mc] = pMl;
        }
        __syncthreads();
    }

    float* ob = out + (size_t)b * L_ * D_;
    const int gr = lane >> 2, gc = (lane & 3) * 2;
#pragma unroll
    for (int tm = 0; tm < 4; ++tm)
#pragma unroll
        for (int tn = 0; tn < 4; ++tn) {
            int row = l0 + m0 + tm * 16 + gr;
            int col = j0 + n0 + tn * 8 + gc;
            float2 cb = *(const float2*)&g_c[b][col];
            *(float2*)(ob + (size_t)row * D_ + col) =
                make_float2(acc[tm][tn][0] + cb.x, acc[tm][tn][1] + cb.y);
            *(float2*)(ob + (size_t)(row + 8) * D_ + col) =
                make_float2(acc[tm][tn][2] + cb.x, acc[tm][tn][3] + cb.y);
        }
}

// ===========================================================================
extern "C" void kernel_launch(void* const* d_in, const int* in_sizes, int n_in,
                              void* d_out, int out_size)
{
    const float* x   = (const float*)d_in[0];
    const float* Wq  = (const float*)d_in[1];
    const float* bq  = (const float*)d_in[2];
    const float* Wk  = (const float*)d_in[3];
    const float* bk  = (const float*)d_in[4];
    const float* Wv  = (const float*)d_in[5];
    const float* bv  = (const float*)d_in[6];
    const float* Wfc = (const float*)d_in[7];
    const float* bfc = (const float*)d_in[8];
    float* out = (float*)d_out;

    k_xtx<<<dim3(NCH, 3, B_), 256>>>(x);
    k_reduce<<<dim3(48, B_), 256>>>();
    k_T<<<dim3(16, B_), 256>>>(Wk);
    k_head<<<dim3(H_, B_, 2), 256>>>(Wq, bq, Wk, bk, Wv, bv);
    k_M<<<dim3(16, B_), 256>>>(Wfc);
    k_c<<<B_, 256>>>(Wfc, bfc);
    k_out<<<dim3(L_ / 128, 2, B_), 256>>>(x, out);
}

// round 17
// speedup vs baseline: 1.1351x; 1.0920x over previous
#include <cuda_runtime.h>
#include <cuda_bf16.h>

#define B_ 4
#define L_ 16384
#define D_ 256
#define H_ 8
#define NCH 16
#define CHUNK 1024   // L_/NCH

// ---- scratch (static device allocations are allowed) ----
__device__ float g_Gpart[B_][NCH][3][128][128];  // ~12.5 MB
__device__ float g_spart[B_][NCH][D_];
__device__ float g_G[B_][D_][D_];
__device__ float g_s[B_][D_];
__device__ float g_T[B_][D_][D_];   // T = Wk @ G
__device__ float g_A[B_][D_][D_];
__device__ float g_r[B_][D_];
__device__ float g_c[B_][D_];
__device__ __nv_bfloat16 g_Mh[B_][D_][D_];   // M split
__device__ __nv_bfloat16 g_Ml[B_][D_][D_];

// ---- mma / ldmatrix helpers ----
__device__ __forceinline__ unsigned sptr(const void* p)
{
    return (unsigned)__cvta_generic_to_shared(p);
}
__device__ __forceinline__ void ldm4t(unsigned r[4], unsigned addr)
{
    asm volatile("ldmatrix.sync.aligned.m8n8.x4.trans.shared.b16 {%0,%1,%2,%3}, [%4];"
                 : "=r"(r[0]), "=r"(r[1]), "=r"(r[2]), "=r"(r[3]) : "r"(addr));
}
__device__ __forceinline__ void ldm4(unsigned r[4], unsigned addr)
{
    asm volatile("ldmatrix.sync.aligned.m8n8.x4.shared.b16 {%0,%1,%2,%3}, [%4];"
                 : "=r"(r[0]), "=r"(r[1]), "=r"(r[2]), "=r"(r[3]) : "r"(addr));
}
__device__ __forceinline__ void mma16816(float* c, const unsigned a[4],
                                         unsigned b0, unsigned b1)
{
    asm("mma.sync.aligned.m16n8k16.row.col.f32.bf16.bf16.f32 "
        "{%0,%1,%2,%3}, {%4,%5,%6,%7}, {%8,%9}, {%0,%1,%2,%3};"
        : "+f"(c[0]), "+f"(c[1]), "+f"(c[2]), "+f"(c[3])
        : "r"(a[0]), "r"(a[1]), "r"(a[2]), "r"(a[3]), "r"(b0), "r"(b1));
}
// split 8 fp32 -> 8 bf16 hi + 8 bf16 lo (packed)
__device__ __forceinline__ void split8(float4 a, float4 b, uint4& hi, uint4& lo)
{
    float v[8] = {a.x, a.y, a.z, a.w, b.x, b.y, b.z, b.w};
    unsigned h[4], l[4];
#pragma unroll
    for (int q = 0; q < 4; ++q) {
        __nv_bfloat162 ph, pl;
        ph.x = __float2bfloat16(v[2*q]);
        ph.y = __float2bfloat16(v[2*q+1]);
        pl.x = __float2bfloat16(v[2*q]   - __bfloat162float(ph.x));
        pl.y = __float2bfloat16(v[2*q+1] - __bfloat162float(ph.y));
        h[q] = *(unsigned*)&ph;
        l[q] = *(unsigned*)&pl;
    }
    hi = make_uint4(h[0], h[1], h[2], h[3]);
    lo = make_uint4(l[0], l[1], l[2], l[3]);
}

// ===========================================================================
// 1) partial G = x^T x via bf16 HMMA (hh + hl + lh); fp32->hi/lo split fused
//    into the smem loaders; colsum fused on diagonal tiles.
// ===========================================================================
__global__ __launch_bounds__(256, 2) void k_xtx(const float* __restrict__ x)
{
    const int chunk = blockIdx.x, tile3 = blockIdx.y, b = blockIdx.z;
    const int i0 = (tile3 == 2) ? 128 : 0;
    const int j0 = (tile3 == 0) ? 0 : 128;
    const bool diag = (tile3 != 1);

    __shared__ __nv_bfloat16 sA[2][2][16][136];   // [buf][hi/lo][k(l)][m(d)]
    __shared__ __nv_bfloat16 sB[2][2][16][136];

    const int t = threadIdx.x, lane = t & 31, w = t >> 5;
    const int wm = w >> 2, wn = w & 3;
    const int m0 = wm * 64, n0 = wn * 32;

    const float* xb = x + ((size_t)b * L_ + (size_t)chunk * CHUNK) * D_;
    const int lr = t >> 4, lc = (t & 15) * 8;    // slab load coords

    float acc[4][4][4];
#pragma unroll
    for (int i = 0; i < 4; ++i)
#pragma unroll
        for (int j = 0; j < 4; ++j)
#pragma unroll
            for (int q = 0; q < 4; ++q) acc[i][j][q] = 0.f;

    float scol[8];
#pragma unroll
    for (int q = 0; q < 8; ++q) scol[q] = 0.f;

    float4 va0, va1, vb0, vb1;
    {
        const float* rp = xb + (size_t)lr * D_;
        va0 = *(const float4*)(rp + i0 + lc);
        va1 = *(const float4*)(rp + i0 + lc + 4);
        if (!diag) {
            vb0 = *(const float4*)(rp + j0 + lc);
            vb1 = *(const float4*)(rp + j0 + lc + 4);
        } else {
            scol[0]+=va0.x; scol[1]+=va0.y; scol[2]+=va0.z; scol[3]+=va0.w;
            scol[4]+=va1.x; scol[5]+=va1.y; scol[6]+=va1.z; scol[7]+=va1.w;
        }
    }
    {
        uint4 hi, lo;
        split8(va0, va1, hi, lo);
        *(uint4*)&sA[0][0][lr][lc] = hi;
        *(uint4*)&sA[0][1][lr][lc] = lo;
        if (!diag) {
            split8(vb0, vb1, hi, lo);
            *(uint4*)&sB[0][0][lr][lc] = hi;
            *(uint4*)&sB[0][1][lr][lc] = lo;
        }
    }
    __syncthreads();

    const int aK = (lane & 7) + ((lane >> 4) << 3);
    const int aM = m0 + (lane & 8);
    const int bK = lane & 15;
    const int bNo = (lane >> 4) << 3;

    const int NS = CHUNK / 16;   // 64
    for (int s = 0; s < NS; ++s) {
        const int buf = s & 1;
        if (s + 1 < NS) {
            const float* rp = xb + (size_t)((s + 1) * 16 + lr) * D_;
            va0 = *(const float4*)(rp + i0 + lc);
            va1 = *(const float4*)(rp + i0 + lc + 4);
            if (!diag) {
                vb0 = *(const float4*)(rp + j0 + lc);
                vb1 = *(const float4*)(rp + j0 + lc + 4);
            } else {
                scol[0]+=va0.x; scol[1]+=va0.y; scol[2]+=va0.z; scol[3]+=va0.w;
                scol[4]+=va1.x; scol[5]+=va1.y; scol[6]+=va1.z; scol[7]+=va1.w;
            }
        }

        unsigned ah[4][4], al[4][4], bh[2][4], bl[2][4];
#pragma unroll
        for (int tm = 0; tm < 4; ++tm) {
            ldm4t(ah[tm], sptr(&sA[buf][0][aK][aM + tm * 16]));
            ldm4t(al[tm], sptr(&sA[buf][1][aK][aM + tm * 16]));
        }
        const __nv_bfloat16 (*pB)[16][136] = diag ? sA[buf] : sB[buf];
#pragma unroll
        for (int tp = 0; tp < 2; ++tp) {
            ldm4t(bh[tp], sptr(&pB[0][bK][n0 + tp * 16 + bNo]));
            ldm4t(bl[tp], sptr(&pB[1][bK][n0 + tp * 16 + bNo]));
        }
#pragma unroll
        for (int tm = 0; tm < 4; ++tm)
#pragma unroll
            for (int tp = 0; tp < 2; ++tp) {
                mma16816(acc[tm][2*tp],   ah[tm], bh[tp][0], bh[tp][1]);
                mma16816(acc[tm][2*tp+1], ah[tm], bh[tp][2], bh[tp][3]);
                mma16816(acc[tm][2*tp],   ah[tm], bl[tp][0], bl[tp][1]);
                mma16816(acc[tm][2*tp+1], ah[tm], bl[tp][2], bl[tp][3]);
                mma16816(acc[tm][2*tp],   al[tm], bh[tp][0], bh[tp][1]);
                mma16816(acc[tm][2*tp+1], al[tm], bh[tp][2], bh[tp][3]);
            }

        if (s + 1 < NS) {
            const int nb = buf ^ 1;
            uint4 hi, lo;
            split8(va0, va1, hi, lo);
            *(uint4*)&sA[nb][0][lr][lc] = hi;
            *(uint4*)&sA[nb][1][lr][lc] = lo;
            if (!diag) {
                split8(vb0, vb1, hi, lo);
                *(uint4*)&sB[nb][0][lr][lc] = hi;
                *(uint4*)&sB[nb][1][lr][lc] = lo;
            }
        }
        __syncthreads();
    }

    const int gr = lane >> 2, gc = (lane & 3) * 2;
#pragma unroll
    for (int tm = 0; tm < 4; ++tm)
#pragma unroll
        for (int tn = 0; tn < 4; ++tn) {
            int row = m0 + tm * 16 + gr;
            int col = n0 + tn * 8 + gc;
            *(float2*)&g_Gpart[b][chunk][tile3][row][col] =
                make_float2(acc[tm][tn][0], acc[tm][tn][1]);
            *(float2*)&g_Gpart[b][chunk][tile3][row + 8][col] =
                make_float2(acc[tm][tn][2], acc[tm][tn][3]);
        }

    if (diag) {   // reduce per-thread column sums (sA no longer needed)
        float* scr = (float*)sA;
#pragma unroll
        for (int q = 0; q < 8; ++q) scr[lr * 128 + lc + q] = scol[q];
        __syncthreads();
        if (t < 128) {
            float sp = 0.f;
#pragma unroll
            for (int r = 0; r < 16; ++r) sp += scr[r * 128 + t];
            g_spart[b][chunk][j0 + t] = sp;
        }
    }
}

// ===========================================================================
// 2) reduce partials -> G (mirroring tile 1), s
// ===========================================================================
__global__ __launch_bounds__(256) void k_reduce()
{
    const int bx = blockIdx.x, b = blockIdx.y;
    const int tile = bx >> 4, seg = bx & 15;
    const int i0 = (tile == 2) ? 128 : 0;
    const int j0 = (tile == 0) ? 0 : 128;
    const int t = threadIdx.x;

    const int e = seg * 256 + t;
    const int u = e >> 5, v4 = (e & 31) << 2;
    float4 sum = make_float4(0.f, 0.f, 0.f, 0.f);
#pragma unroll
    for (int ch = 0; ch < NCH; ++ch) {
        float4 p = *(const float4*)&g_Gpart[b][ch][tile][u][v4];
        sum.x += p.x; sum.y += p.y; sum.z += p.z; sum.w += p.w;
    }
    *(float4*)&g_G[b][i0 + u][j0 + v4] = sum;
    if (tile == 1) {
        g_G[b][j0 + v4 + 0][i0 + u] = sum.x;
        g_G[b][j0 + v4 + 1][i0 + u] = sum.y;
        g_G[b][j0 + v4 + 2][i0 + u] = sum.z;
        g_G[b][j0 + v4 + 3][i0 + u] = sum.w;
    }
    if (seg == 0 && tile != 1 && t < 128) {
        float s = 0.f;
#pragma unroll
        for (int ch = 0; ch < NCH; ++ch) s += g_spart[b][ch][j0 + t];
        g_s[b][j0 + t] = s;
    }
}

// ===========================================================================
// 3) T[b] = Wk @ G[b]    (NN, 64x64 tiles, 4x4 micro)
// ===========================================================================
__global__ __launch_bounds__(256) void k_T(const float* __restrict__ Wk)
{
    const int tile = blockIdx.x, b = blockIdx.y;
    const int i0 = (tile >> 2) << 6, j0 = (tile & 3) << 6;
    __shared__ float As[16][65];
    __shared__ __align__(16) float Bs[16][68];
    const int t = threadIdx.x, tx = t & 15, ty = t >> 4;
    const int au = t >> 2, aq = (t & 3) << 2;
    const int br = t >> 4, bc = (t & 15) << 2;

    float acc[4][4] = {};
    for (int k0 = 0; k0 < D_; k0 += 16) {
        float4 av = *(const float4*)&Wk[(i0 + au) * D_ + k0 + aq];
        As[aq+0][au] = av.x; As[aq+1][au] = av.y;
        As[aq+2][au] = av.z; As[aq+3][au] = av.w;
        *(float4*)&Bs[br][bc] = *(const float4*)&g_G[b][k0 + br][j0 + bc];
        __syncthreads();
#pragma unroll
        for (int kk = 0; kk < 16; ++kk) {
            float a[4], bb[4];
#pragma unroll
            for (int i = 0; i < 4; ++i) a[i] = As[kk][(ty << 2) + i];
#pragma unroll
            for (int j2 = 0; j2 < 4; ++j2) bb[j2] = Bs[kk][(tx << 2) + j2];
#pragma unroll
            for (int i = 0; i < 4; ++i)
#pragma unroll
                for (int j2 = 0; j2 < 4; ++j2) acc[i][j2] += a[i] * bb[j2];
        }
        __syncthreads();
    }
#pragma unroll
    for (int i = 0; i < 4; ++i) {
        float4 v = make_float4(acc[i][0], acc[i][1], acc[i][2], acc[i][3]);
        *(float4*)&g_T[b][i0 + (ty << 2) + i][j0 + (tx << 2)] = v;
    }
}

// ===========================================================================
// 4) per (b,h,half): P_h (32x32) incl. bias rank-1 terms, then a 16-column
//    slice of the A-block (split over blockIdx.z for 2x occupancy); r in half 0.
// ===========================================================================
__global__ __launch_bounds__(256) void k_head(
    const float* __restrict__ Wq, const float* __restrict__ bq,
    const float* __restrict__ Wk, const float* __restrict__ bk,
    const float* __restrict__ Wv, const float* __restrict__ bv)
{
    const int h = blockIdx.x, b = blockIdx.y, half = blockIdx.z;
    const int hbase = h * 32;
    const int t = threadIdx.x, lane = t & 31, w = t >> 5;
    const float invL = 1.f / (float)L_;

    __shared__ __align__(16) float Wvs[32][260];
    __shared__ __align__(16) float Ts[32][260];
    __shared__ __align__(16) float sv[256];
    __shared__ float uu[32], ww[32];
    __shared__ __align__(16) float Psm[32][36];

    sv[t] = g_s[b][t];
#pragma unroll
    for (int e0 = 0; e0 < 8; ++e0) {
        int e = t + e0 * 256;
        int row = e >> 6, c4 = (e & 63) << 2;
        *(float4*)&Wvs[row][c4] = *(const float4*)&Wv[(hbase + row) * D_ + c4];
        *(float4*)&Ts[row][c4]  = *(const float4*)&g_T[b][hbase + row][c4];
    }
    __syncthreads();

    {
        int r = t >> 3, l8 = t & 7;
        float pk = 0.f, pv = 0.f;
#pragma unroll
        for (int k = l8 * 4; k < D_; k += 32) {
            float4 wk4 = *(const float4*)&Wk[(hbase + r) * D_ + k];
            float4 wv4 = *(const float4*)&Wvs[r][k];
            float4 s4  = *(const float4*)&sv[k];
            pk += wk4.x * s4.x + wk4.y * s4.y + wk4.z * s4.z + wk4.w * s4.w;
            pv += wv4.x * s4.x + wv4.y * s4.y + wv4.z * s4.z + wv4.w * s4.w;
        }
#pragma unroll
        for (int off = 4; off > 0; off >>= 1) {
            pk += __shfl_down_sync(0xffffffffu, pk, off);
            pv += __shfl_down_sync(0xffffffffu, pv, off);
        }
        if (l8 == 0) { uu[r] = pk; ww[r] = pv; }
    }
    __syncthreads();

#pragma unroll
    for (int q = 0; q < 4; ++q) {
        int i = w + 8 * q;
        float d0 = 0.f, d1 = 0.f, d2 = 0.f, d3 = 0.f;
#pragma unroll
        for (int k4 = 0; k4 < 64; ++k4) {
            float4 tv = *(const float4*)&Ts[i][k4 << 2];
            float4 wv = *(const float4*)&Wvs[lane][k4 << 2];
            d0 += tv.x * wv.x; d1 += tv.y * wv.y;
            d2 += tv.z * wv.z; d3 += tv.w * wv.w;
        }
        float dot = (d0 + d1) + (d2 + d3);
        Psm[i][lane] = (dot + uu[i] * bv[hbase + lane] + bk[hbase + i] * ww[lane]) * invL
                       + bk[hbase + i] * bv[hbase + lane];
    }
    __syncthreads();

    // A-slice: 16 columns (this block's half)
    {
        float acc[16];
#pragma unroll
        for (int j = 0; j < 16; ++j) acc[j] = 0.f;
#pragma unroll 4
        for (int i = 0; i < 32; ++i) {
            float wq = Wq[(hbase + i) * D_ + t];
#pragma unroll
            for (int j4 = 0; j4 < 4; ++j4) {
                float4 p4 = *(const float4*)&Psm[i][half * 16 + (j4 << 2)];
                acc[4*j4+0] += wq * p4.x; acc[4*j4+1] += wq * p4.y;
                acc[4*j4+2] += wq * p4.z; acc[4*j4+3] += wq * p4.w;
            }
        }
#pragma unroll
        for (int j4 = 0; j4 < 4; ++j4)
            *(float4*)&g_A[b][t][hbase + half * 16 + (j4 << 2)] =
                make_float4(acc[4*j4], acc[4*j4+1], acc[4*j4+2], acc[4*j4+3]);
    }

    if (half == 0 && t < 32) {
        float p = 0.f;
#pragma unroll
        for (int i = 0; i < 32; ++i) p += bq[hbase + i] * Psm[i][t];
        g_r[b][hbase + t] = p;
    }
}

// ===========================================================================
// 5) M[b] = A[b] @ Wfc^T  (NT, 64x64 tiles) -> bf16 hi/lo.
//    Blocks with i0==0 also accumulate c[j0..j0+64] = Wfc_rows @ r from the
//    already-staged Bs tiles (smem-only, coalesced), then add bfc.
// ===========================================================================
__global__ __launch_bounds__(256) void k_M(const float* __restrict__ Wfc,
                                           const float* __restrict__ bfc)
{
    const int tile = blockIdx.x, b = blockIdx.y;
    const int i0 = (tile >> 2) << 6, j0 = (tile & 3) << 6;
    const bool doc = (tile < 4);   // i0 == 0
    __shared__ float As[16][65];
    __shared__ float Bs[16][65];
    __shared__ float rsm[256];
    const int t = threadIdx.x, tx = t & 15, ty = t >> 4;
    const int au = t >> 2, aq = (t & 3) << 2;

    if (doc) rsm[t] = g_r[b][t];

    float acc[4][4] = {};
    float cpart = 0.f;
    for (int k0 = 0; k0 < D_; k0 += 16) {
        float4 av = *(const float4*)&g_A[b][i0 + au][k0 + aq];
        As[aq+0][au] = av.x; As[aq+1][au] = av.y;
        As[aq+2][au] = av.z; As[aq+3][au] = av.w;
        float4 bv4 = *(const float4*)&Wfc[(j0 + au) * D_ + k0 + aq];
        Bs[aq+0][au] = bv4.x; Bs[aq+1][au] = bv4.y;
        Bs[aq+2][au] = bv4.z; Bs[aq+3][au] = bv4.w;
        __syncthreads();
#pragma unroll
        for (int kk = 0; kk < 16; ++kk) {
            float a[4], bb[4];
#pragma unroll
            for (int i = 0; i < 4; ++i) a[i]  = As[kk][(ty << 2) + i];
#pragma unroll
            for (int j2 = 0; j2 < 4; ++j2) bb[j2] = Bs[kk][(tx << 2) + j2];
#pragma unroll
            for (int i = 0; i < 4; ++i)
#pragma unroll
                for (int j2 = 0; j2 < 4; ++j2) acc[i][j2] += a[i] * bb[j2];
        }
        if (doc && t < 64) {
#pragma unroll
            for (int kk = 0; kk < 16; ++kk)
                cpart += Bs[kk][t] * rsm[k0 + kk];
        }
        __syncthreads();
    }
#pragma unroll
    for (int i = 0; i < 4; ++i) {
        int row = i0 + (ty << 2) + i, col = j0 + (tx << 2);
#pragma unroll
        for (int q = 0; q < 4; ++q) {
            float v = acc[i][q];
            __nv_bfloat16 hh = __float2bfloat16(v);
            g_Mh[b][row][col + q] = hh;
            g_Ml[b][row][col + q] = __float2bfloat16(v - __bfloat162float(hh));
        }
    }
    if (doc && t < 64)
        g_c[b][j0 + t] = cpart + bfc[j0 + t];
}

// ===========================================================================
// 6) final[b] = x[b] @ M[b] + 1 c[b]^T  via bf16 HMMA (hh + hl + lh);
//    fp32->hi/lo split of x fused into the smem loader.
//    PERSISTENT: 256 blocks (single wave at 2 CTAs/SM), 4 tiles each.
// ===========================================================================
__global__ __launch_bounds__(256, 2) void k_out(const float* __restrict__ x,
                                                float* __restrict__ out)
{
    const int t = threadIdx.x, lane = t & 31, w = t >> 5;
    const int wm = w >> 2, wn = w & 3;
    const int m0 = wm * 64, n0 = wn * 32;

    __shared__ __nv_bfloat16 sX[2][2][128][24];   // [buf][hi/lo][m(l)][k]
    __shared__ __nv_bfloat16 sM[2][2][16][136];   // [buf][hi/lo][k][n]

    const int xr = t >> 1, xk = (t & 1) * 8;     // X slab load coords
    const int mr = t >> 4, mc = (t & 15) * 8;    // M slab load coords

    const int aR = m0 + (lane & 7) + 8 * ((lane >> 3) & 1);
    const int aC = (lane >> 4) << 3;
    const int bK = lane & 15;
    const int bNo = (lane >> 4) << 3;
    const int gr = lane >> 2, gc = (lane & 3) * 2;

    for (int it = 0; it < 4; ++it) {
        const int tile = (blockIdx.x << 2) + it;      // 0..1023
        const int dt = tile & 1, lt = (tile >> 1) & 127, b = tile >> 8;
        const int l0 = lt * 128, j0 = dt * 128;
        const float* xb = x + ((size_t)b * L_ + l0) * D_;

        float acc[4][4][4];
#pragma unroll
        for (int i = 0; i < 4; ++i)
#pragma unroll
            for (int j = 0; j < 4; ++j)
#pragma unroll
                for (int q = 0; q < 4; ++q) acc[i][j][q] = 0.f;

        float4 vx0, vx1;
        uint4 pMh, pMl;
        vx0 = *(const float4*)(xb + (size_t)xr * D_ + xk);
        vx1 = *(const float4*)(xb + (size_t)xr * D_ + xk + 4);
        pMh = *(const uint4*)&g_Mh[b][mr][j0 + mc];
        pMl = *(const uint4*)&g_Ml[b][mr][j0 + mc];
        {
            uint4 hi, lo;
            split8(vx0, vx1, hi, lo);
            *(uint4*)&sX[0][0][xr][xk] = hi;
            *(uint4*)&sX[0][1][xr][xk] = lo;
        }
        *(uint4*)&sM[0][0][mr][mc] = pMh;
        *(uint4*)&sM[0][1][mr][mc] = pMl;
        __syncthreads();

        const int NS = D_ / 16;   // 16
        for (int s = 0; s < NS; ++s) {
            const int buf = s & 1;
            if (s + 1 < NS) {
                int k0 = (s + 1) * 16;
                vx0 = *(const float4*)(xb + (size_t)xr * D_ + k0 + xk);
                vx1 = *(const float4*)(xb + (size_t)xr * D_ + k0 + xk + 4);
                pMh = *(const uint4*)&g_Mh[b][k0 + mr][j0 + mc];
                pMl = *(const uint4*)&g_Ml[b][k0 + mr][j0 + mc];
            }

            unsigned ah[4][4], al[4][4], bh[2][4], bl[2][4];
#pragma unroll
            for (int tm = 0; tm < 4; ++tm) {
                ldm4(ah[tm], sptr(&sX[buf][0][aR + tm * 16][aC]));
                ldm4(al[tm], sptr(&sX[buf][1][aR + tm * 16][aC]));
            }
#pragma unroll
            for (int tp = 0; tp < 2; ++tp) {
                ldm4t(bh[tp], sptr(&sM[buf][0][bK][n0 + tp * 16 + bNo]));
                ldm4t(bl[tp], sptr(&sM[buf][1][bK][n0 + tp * 16 + bNo]));
            }
#pragma unroll
            for (int tm = 0; tm < 4; ++tm)
#pragma unroll
                for (int tp = 0; tp < 2; ++tp) {
                    mma16816(acc[tm][2*tp],   ah[tm], bh[tp][0], bh[tp][1]);
                    mma16816(acc[tm][2*tp+1], ah[tm], bh[tp][2], bh[tp][3]);
                    mma16816(acc[tm][2*tp],   ah[tm], bl[tp][0], bl[tp][1]);
                    mma16816(acc[tm][2*tp+1], ah[tm], bl[tp][2], bl[tp][3]);
                    mma16816(acc[tm][2*tp],   al[tm], bh[tp][0], bh[tp][1]);
                    mma16816(acc[tm][2*tp+1], al[tm], bh[tp][2], bh[tp][3]);
                }

            if (s + 1 < NS) {
                const int nb = buf ^ 1;
                uint4 hi, lo;
                split8(vx0, vx1, hi, lo);
                *(uint4*)&sX[nb][0][xr][xk] = hi;
                *(uint4*)&sX[nb][1][xr][xk] = lo;
                *(uint4*)&sM[nb][0][mr][mc] = pMh;
                *(uint4*)&sM[nb][1][mr][mc] = pMl;
            }
            __syncthreads();
        }

        float* ob = out + (size_t)b * L_ * D_;
#pragma unroll
        for (int tm = 0; tm < 4; ++tm)
#pragma unroll
            for (int tn = 0; tn < 4; ++tn) {
                int row = l0 + m0 + tm * 16 + gr;
                int col = j0 + n0 + tn * 8 + gc;
                float2 cb = *(const float2*)&g_c[b][col];
                *(float2*)(ob + (size_t)row * D_ + col) =
                    make_float2(acc[tm][tn][0] + cb.x, acc[tm][tn][1] + cb.y);
                *(float2*)(ob + (size_t)(row + 8) * D_ + col) =
                    make_float2(acc[tm][tn][2] + cb.x, acc[tm][tn][3] + cb.y);
            }
    }
}

// ===========================================================================
extern "C" void kernel_launch(void* const* d_in, const int* in_sizes, int n_in,
                              void* d_out, int out_size)
{
    const float* x   = (const float*)d_in[0];
    const float* Wq  = (const float*)d_in[1];
    const float* bq  = (const float*)d_in[2];
    const float* Wk  = (const float*)d_in[3];
    const float* bk  = (const float*)d_in[4];
    const float* Wv  = (const float*)d_in[5];
    const float* bv  = (const float*)d_in[6];
    const float* Wfc = (const float*)d_in[7];
    const float* bfc = (const float*)d_in[8];
    float* out = (float*)d_out;

    k_xtx<<<dim3(NCH, 3, B_), 256>>>(x);
    k_reduce<<<dim3(48, B_), 256>>>();
    k_T<<<dim3(16, B_), 256>>>(Wk);
    k_head<<<dim3(H_, B_, 2), 256>>>(Wq, bq, Wk, bk, Wv, bv);
    k_M<<<dim3(16, B_), 256>>>(Wfc, bfc);
    k_out<<<256, 256>>>(x, out);
}